// round 13
// baseline (speedup 1.0000x reference)
#include <cuda_runtime.h>
#include <cuda_bf16.h>

#define B_FIXED  4096
#define D_FIXED  256
#define MAX_GAP  5
#define LOSS_W   0.1
#define NBLK     128
#define NTHR     512
#define NWARP    (NTHR / 32)            // 16
#define ROWS_PB  (B_FIXED / NBLK)       // 32 rows per block (strided)
#define KEYS_PT  8                      // keys per thread
#define PAIR_CAP 1024

__device__ double       g_ploss[NBLK];
__device__ unsigned int g_pcnt[NBLK];
__device__ unsigned int g_done;

__global__ void __launch_bounds__(NTHR)
main_kernel(const float* __restrict__ emb,
            const int*   __restrict__ frames,
            const int*   __restrict__ vids,
            float*       __restrict__ out)
{
    __shared__ unsigned short skey[B_FIXED];     // 8 KB
    __shared__ unsigned int   pairs[PAIR_CAP];   // 4 KB
    __shared__ int            s_np;
    __shared__ double         s_loss[NWARP];
    __shared__ unsigned int   s_cnt[NWARP];
    __shared__ bool           s_last;

    const int tid  = threadIdx.x;
    const int warp = tid >> 5;
    const int lane = tid & 31;

    // ---- 1. build keys: 8 elements/thread, one uint4 smem store; keep own
    //         keys packed in registers. key = (vid<<10)|frame; mask reduces
    //         to |key_i - key_j| <= 5 (cross-vid key gap >= 25).
    uint4 kw;
    {
        const int4* f4 = (const int4*)frames;
        const int4* v4 = (const int4*)vids;
        int4 fa = f4[tid * 2],     fb = f4[tid * 2 + 1];
        int4 va = v4[tid * 2],     vb = v4[tid * 2 + 1];
        kw.x = (unsigned int)((va.x << 10) | fa.x)
             | ((unsigned int)((va.y << 10) | fa.y) << 16);
        kw.y = (unsigned int)((va.z << 10) | fa.z)
             | ((unsigned int)((va.w << 10) | fa.w) << 16);
        kw.z = (unsigned int)((vb.x << 10) | fb.x)
             | ((unsigned int)((vb.y << 10) | fb.y) << 16);
        kw.w = (unsigned int)((vb.z << 10) | fb.z)
             | ((unsigned int)((vb.w << 10) | fb.w) << 16);
        ((uint4*)skey)[tid] = kw;
    }
    if (tid == 0) s_np = 0;
    __syncthreads();

    // ---- 2. preload 32 row keys (broadcast LDS) ----
    unsigned int rk[ROWS_PB];
    #pragma unroll
    for (int m = 0; m < ROWS_PB; m++)
        rk[m] = skey[blockIdx.x + m * NBLK];

    // ---- 3. SIMD scan: 2 halfword compares per op, rare slow path ----
    {
        const unsigned int kws[4] = { kw.x, kw.y, kw.z, kw.w };
        const int jbase = tid * KEYS_PT;
        const unsigned int GAP2 = 0x00050005u;

        #pragma unroll
        for (int m = 0; m < ROWS_PB; m++) {
            const int r   = blockIdx.x + m * NBLK;
            const unsigned int kr2 = rk[m] * 0x00010001u;

            unsigned int hit =
                  __vcmpleu2(__vabsdiffu2(kws[0], kr2), GAP2)
                | __vcmpleu2(__vabsdiffu2(kws[1], kr2), GAP2)
                | __vcmpleu2(__vabsdiffu2(kws[2], kr2), GAP2)
                | __vcmpleu2(__vabsdiffu2(kws[3], kr2), GAP2);

            if (hit) {                         // rare: ~90 executions/block
                const int kr = (int)rk[m];
                #pragma unroll
                for (int w = 0; w < 4; w++) {
                    const int ka = (int)(kws[w] & 0xFFFFu);
                    const int kb = (int)(kws[w] >> 16);
                    const int j0 = jbase + w * 2;
                    const int j1 = j0 + 1;
                    const int d0 = abs(ka - kr);
                    const int d1 = abs(kb - kr);
                    if (d0 <= MAX_GAP && j0 > r) {
                        int idx = atomicAdd(&s_np, 1);
                        if (idx < PAIR_CAP)
                            pairs[idx] = ((unsigned int)d0 << 24)
                                       | ((unsigned int)r << 12)
                                       | (unsigned int)j0;
                    }
                    if (d1 <= MAX_GAP && j1 > r) {
                        int idx = atomicAdd(&s_np, 1);
                        if (idx < PAIR_CAP)
                            pairs[idx] = ((unsigned int)d1 << 24)
                                       | ((unsigned int)r << 12)
                                       | (unsigned int)j1;
                    }
                }
            }
        }
    }
    __syncthreads();

    // ---- 4. drain: one warp per pair ----
    double       loss = 0.0;
    unsigned int cnt_acc = 0;
    {
        const int np = min(s_np, PAIR_CAP);
        for (int p = warp; p < np; p += NWARP) {
            const unsigned int pk = pairs[p];
            const int df = pk >> 24;
            const int i  = (pk >> 12) & 0xFFF;
            const int j  = pk & 0xFFF;
            const float4* ri = (const float4*)(emb + (size_t)i * D_FIXED);
            const float4* rj = (const float4*)(emb + (size_t)j * D_FIXED);

            float4 a0 = __ldg(&ri[lane]);        float4 b0 = __ldg(&rj[lane]);
            float4 a1 = __ldg(&ri[lane + 32]);   float4 b1 = __ldg(&rj[lane + 32]);

            float d0 = a0.x - b0.x, d1 = a0.y - b0.y;
            float d2 = a0.z - b0.z, d3 = a0.w - b0.w;
            float acc = d0 * d0;
            acc = fmaf(d1, d1, acc); acc = fmaf(d2, d2, acc); acc = fmaf(d3, d3, acc);
            d0 = a1.x - b1.x; d1 = a1.y - b1.y; d2 = a1.z - b1.z; d3 = a1.w - b1.w;
            acc = fmaf(d0, d0, acc); acc = fmaf(d1, d1, acc);
            acc = fmaf(d2, d2, acc); acc = fmaf(d3, d3, acc);

            #pragma unroll
            for (int off = 16; off > 0; off >>= 1)
                acc += __shfl_down_sync(0xFFFFFFFFu, acc, off);

            if (lane == 0) {
                float w = 1.0f / (1.0f + (float)df);
                loss += (double)(acc * w * (1.0f / (float)D_FIXED));
                cnt_acc += 1u;
            }
        }
    }

    // ---- 5. block reduction ----
    #pragma unroll
    for (int off = 16; off > 0; off >>= 1) {
        loss    += __shfl_down_sync(0xFFFFFFFFu, loss, off);
        cnt_acc += __shfl_down_sync(0xFFFFFFFFu, cnt_acc, off);
    }
    if (lane == 0) { s_loss[warp] = loss; s_cnt[warp] = cnt_acc; }
    __syncthreads();

    if (warp == 0) {
        double       l = (lane < NWARP) ? s_loss[lane] : 0.0;
        unsigned int c = (lane < NWARP) ? s_cnt[lane]  : 0u;
        #pragma unroll
        for (int off = 8; off > 0; off >>= 1) {
            l += __shfl_down_sync(0xFFFFFFFFu, l, off);
            c += __shfl_down_sync(0xFFFFFFFFu, c, off);
        }
        if (lane == 0) { g_ploss[blockIdx.x] = l; g_pcnt[blockIdx.x] = c; }
    }

    // ---- 6. last-block-done grid reduction ----
    __threadfence();
    if (tid == 0) {
        unsigned int prev = atomicAdd(&g_done, 1u);
        s_last = (prev == NBLK - 1);
    }
    __syncthreads();

    if (s_last) {
        __threadfence();
        double       l = (tid < NBLK) ? g_ploss[tid] : 0.0;
        unsigned int c = (tid < NBLK) ? g_pcnt[tid]  : 0u;
        #pragma unroll
        for (int off = 16; off > 0; off >>= 1) {
            l += __shfl_down_sync(0xFFFFFFFFu, l, off);
            c += __shfl_down_sync(0xFFFFFFFFu, c, off);
        }
        if (lane == 0) { s_loss[warp] = l; s_cnt[warp] = c; }
        __syncthreads();
        if (tid == 0) {
            double L = 0.0; unsigned int C = 0u;
            #pragma unroll
            for (int w = 0; w < NWARP; w++) { L += s_loss[w]; C += s_cnt[w]; }
            double Cd = (double)C;
            if (Cd < 1.0) Cd = 1.0;
            out[0] = (float)(LOSS_W * L / Cd);
            g_done = 0;
        }
    }
}

// ---------------------------------------------------------------------------
extern "C" void kernel_launch(void* const* d_in, const int* in_sizes, int n_in,
                              void* d_out, int out_size)
{
    const float* emb    = (const float*)d_in[0];
    const int*   frames = (const int*)d_in[1];
    const int*   vids   = (const int*)d_in[2];
    float*       out    = (float*)d_out;

    main_kernel<<<NBLK, NTHR>>>(emb, frames, vids, out);
}

// round 14
// speedup vs baseline: 1.7477x; 1.7477x over previous
#include <cuda_runtime.h>
#include <cuda_bf16.h>

#define B_FIXED  4096
#define D_FIXED  256
#define MAX_GAP  5
#define LOSS_W   0.1
#define NBLK     128
#define NTHR     1024
#define NWARP    (NTHR / 32)            // 32
#define NBINS    16384                  // key = (vid<<10) | frame
#define NWORDS   (NBINS / 2)            // u16-packed bins (8192 words)
#define WPW      (NWORDS / NWARP)       // 256 words per warp
#define WAVES    (WPW / 32)             // 8 coalesced waves per warp
#define PAIR_CAP 2048
#define POS_PER_BLK (B_FIXED / NBLK)    // 32

__device__ double       g_ploss[NBLK];
__device__ unsigned int g_pcnt[NBLK];
__device__ unsigned int g_done;

// Dynamic smem (56 KB):
//   u32 bins[NWORDS]    32 KB (two u16 bins per word)
//   u32 scratch[2048]    8 KB (tkey during sort, pairs after)
//   u16 skey[B]          8 KB
//   u16 sid [B]          8 KB
#define SMEM_BYTES (NWORDS*4 + PAIR_CAP*4 + B_FIXED*2 + B_FIXED*2)

__device__ __forceinline__ int bin_fetch_inc(unsigned int* bins, int k)
{
    const int sh = (k & 1) * 16;
    unsigned int prev = atomicAdd(&bins[k >> 1], 1u << sh);
    return (int)((prev >> sh) & 0xFFFFu);
}

__device__ __forceinline__ float pair_dist2(const float* __restrict__ emb,
                                            unsigned int pk, int lane)
{
    const int i = (pk >> 12) & 0xFFF;
    const int j = pk & 0xFFF;
    const float4* ri = (const float4*)(emb + (size_t)i * D_FIXED);
    const float4* rj = (const float4*)(emb + (size_t)j * D_FIXED);
    float4 a0 = __ldg(&ri[lane]);        float4 b0 = __ldg(&rj[lane]);
    float4 a1 = __ldg(&ri[lane + 32]);   float4 b1 = __ldg(&rj[lane + 32]);
    float d0 = a0.x - b0.x, d1 = a0.y - b0.y;
    float d2 = a0.z - b0.z, d3 = a0.w - b0.w;
    float acc = d0 * d0;
    acc = fmaf(d1, d1, acc); acc = fmaf(d2, d2, acc); acc = fmaf(d3, d3, acc);
    d0 = a1.x - b1.x; d1 = a1.y - b1.y; d2 = a1.z - b1.z; d3 = a1.w - b1.w;
    acc = fmaf(d0, d0, acc); acc = fmaf(d1, d1, acc);
    acc = fmaf(d2, d2, acc); acc = fmaf(d3, d3, acc);
    #pragma unroll
    for (int off = 16; off > 0; off >>= 1)
        acc += __shfl_down_sync(0xFFFFFFFFu, acc, off);
    return acc;
}

__global__ void __launch_bounds__(NTHR)
main_kernel(const float* __restrict__ emb,
            const int*   __restrict__ frames,
            const int*   __restrict__ vids,
            float*       __restrict__ out)
{
    extern __shared__ unsigned int smem_raw[];
    unsigned int*   bins    = smem_raw;
    unsigned int*   scratch = bins + NWORDS;          // tkey then pairs
    unsigned short* skey    = (unsigned short*)(scratch + PAIR_CAP);
    unsigned short* sid     = skey + B_FIXED;

    __shared__ int          s_np;
    __shared__ int          s_scan[NWARP];
    __shared__ double       s_loss[NWARP];
    __shared__ unsigned int s_cnt[NWARP];
    __shared__ bool         s_last;

    const int tid  = threadIdx.x;
    const int warp = tid >> 5;
    const int lane = tid & 31;

    // ---- 1. zero bins: 2048 uint4 / 1024 thr = 2 per thread ----
    {
        uint4* b4 = (uint4*)bins;
        #pragma unroll
        for (int t = tid; t < NWORDS / 4; t += NTHR)
            b4[t] = make_uint4(0, 0, 0, 0);
    }
    if (tid == 0) s_np = 0;
    __syncthreads();

    // ---- 2. histogram + key cache: exactly 1 int4 group per thread ----
    {
        const int4* f4 = (const int4*)frames;
        const int4* v4 = (const int4*)vids;
        int4 f = __ldg(&f4[tid]);
        int4 v = __ldg(&v4[tid]);
        int k0 = (v.x << 10) | f.x;
        int k1 = (v.y << 10) | f.y;
        int k2 = (v.z << 10) | f.z;
        int k3 = (v.w << 10) | f.w;
        atomicAdd(&bins[k0 >> 1], 1u << ((k0 & 1) * 16));
        atomicAdd(&bins[k1 >> 1], 1u << ((k1 & 1) * 16));
        atomicAdd(&bins[k2 >> 1], 1u << ((k2 & 1) * 16));
        atomicAdd(&bins[k3 >> 1], 1u << ((k3 & 1) * 16));
        uint2 pk;
        pk.x = (unsigned int)k0 | ((unsigned int)k1 << 16);
        pk.y = (unsigned int)k2 | ((unsigned int)k3 << 16);
        ((uint2*)scratch)[tid] = pk;
    }
    __syncthreads();

    // ---- 3. exclusive prefix sum (warp owns 256 words, 8 coalesced waves) ----
    {
        const int wbase = warp * WPW;

        unsigned int lsum = 0;
        #pragma unroll
        for (int k = 0; k < WAVES; k++) {
            unsigned int word = bins[wbase + k * 32 + lane];
            lsum += (word & 0xFFFFu) + (word >> 16);
        }
        #pragma unroll
        for (int off = 16; off > 0; off >>= 1)
            lsum += __shfl_down_sync(0xFFFFFFFFu, lsum, off);
        if (lane == 0) s_scan[warp] = (int)lsum;
        __syncthreads();

        if (warp == 0) {                 // NWARP == 32: full-warp scan, safe
            unsigned int wv = (unsigned int)s_scan[lane];
            unsigned int orig = wv;
            #pragma unroll
            for (int off = 1; off < 32; off <<= 1) {
                unsigned int n = __shfl_up_sync(0xFFFFFFFFu, wv, off);
                if (lane >= off) wv += n;
            }
            s_scan[lane] = (int)(wv - orig);
        }
        __syncthreads();

        unsigned int run = (unsigned int)s_scan[warp];
        #pragma unroll
        for (int k = 0; k < WAVES; k++) {
            const int idx = wbase + k * 32 + lane;
            unsigned int word = bins[idx];
            unsigned int lo = word & 0xFFFFu, hi = word >> 16;
            unsigned int s  = lo + hi;
            unsigned int v  = s;
            #pragma unroll
            for (int off = 1; off < 32; off <<= 1) {
                unsigned int n = __shfl_up_sync(0xFFFFFFFFu, v, off);
                if (lane >= off) v += n;
            }
            unsigned int plo = run + (v - s);
            unsigned int phi = plo + lo;
            bins[idx] = plo | (phi << 16);
            run += __shfl_sync(0xFFFFFFFFu, v, 31);
        }
    }
    __syncthreads();

    // ---- 4. scatter: 1 int4 group per thread ----
    {
        uint2 pk = ((const uint2*)scratch)[tid];
        int k0 = (int)(pk.x & 0xFFFFu), k1 = (int)(pk.x >> 16);
        int k2 = (int)(pk.y & 0xFFFFu), k3 = (int)(pk.y >> 16);
        int i0 = tid * 4;
        int p0 = bin_fetch_inc(bins, k0);
        int p1 = bin_fetch_inc(bins, k1);
        int p2 = bin_fetch_inc(bins, k2);
        int p3 = bin_fetch_inc(bins, k3);
        skey[p0] = (unsigned short)k0;  sid[p0] = (unsigned short)(i0);
        skey[p1] = (unsigned short)k1;  sid[p1] = (unsigned short)(i0 + 1);
        skey[p2] = (unsigned short)k2;  sid[p2] = (unsigned short)(i0 + 2);
        skey[p3] = (unsigned short)k3;  sid[p3] = (unsigned short)(i0 + 3);
    }
    __syncthreads();                                    // scratch reused as pairs

    // ---- 5. pair enumeration: sorted-window scan ----
    if (tid < POS_PER_BLK) {
        const int p  = blockIdx.x * POS_PER_BLK + tid;
        const int kp = skey[p];
        const int ip = sid[p];
        for (int q = p + 1; q < B_FIXED; q++) {
            const int dk = (int)skey[q] - kp;           // frame diff iff same vid
            if (dk > MAX_GAP) break;                    // vid change => dk >= 25
            int idx = atomicAdd(&s_np, 1);
            if (idx < PAIR_CAP)
                scratch[idx] = ((unsigned int)dk << 24)
                             | ((unsigned int)ip << 12)
                             | (unsigned int)sid[q];
        }
    }
    __syncthreads();

    // ---- 6. drain: each warp processes TWO pairs concurrently (MLP x2) ----
    double       loss = 0.0;
    unsigned int cnt_acc = 0;
    {
        const int np = min(s_np, PAIR_CAP);
        for (int p = warp; p < np; p += 2 * NWARP) {
            const int p2 = p + NWARP;
            const unsigned int pk0 = scratch[p];
            const unsigned int pk1 = (p2 < np) ? scratch[p2] : pk0;

            float acc0 = pair_dist2(emb, pk0, lane);
            float acc1 = pair_dist2(emb, pk1, lane);

            if (lane == 0) {
                float w0 = 1.0f / (1.0f + (float)(pk0 >> 24));
                loss += (double)(acc0 * w0 * (1.0f / (float)D_FIXED));
                cnt_acc += 1u;
                if (p2 < np) {
                    float w1 = 1.0f / (1.0f + (float)(pk1 >> 24));
                    loss += (double)(acc1 * w1 * (1.0f / (float)D_FIXED));
                    cnt_acc += 1u;
                }
            }
        }
    }

    // ---- 7. block reduction ----
    #pragma unroll
    for (int off = 16; off > 0; off >>= 1) {
        loss    += __shfl_down_sync(0xFFFFFFFFu, loss, off);
        cnt_acc += __shfl_down_sync(0xFFFFFFFFu, cnt_acc, off);
    }
    if (lane == 0) { s_loss[warp] = loss; s_cnt[warp] = cnt_acc; }
    __syncthreads();

    if (warp == 0) {                      // NWARP == 32: full-warp reduce
        double       l = s_loss[lane];
        unsigned int c = s_cnt[lane];
        #pragma unroll
        for (int off = 16; off > 0; off >>= 1) {
            l += __shfl_down_sync(0xFFFFFFFFu, l, off);
            c += __shfl_down_sync(0xFFFFFFFFu, c, off);
        }
        if (lane == 0) { g_ploss[blockIdx.x] = l; g_pcnt[blockIdx.x] = c; }
    }

    // ---- 8. last-block-done grid reduction ----
    __threadfence();
    if (tid == 0) {
        unsigned int prev = atomicAdd(&g_done, 1u);
        s_last = (prev == NBLK - 1);
    }
    __syncthreads();

    if (s_last) {
        __threadfence();
        double       l = (tid < NBLK) ? g_ploss[tid] : 0.0;
        unsigned int c = (tid < NBLK) ? g_pcnt[tid]  : 0u;
        #pragma unroll
        for (int off = 16; off > 0; off >>= 1) {
            l += __shfl_down_sync(0xFFFFFFFFu, l, off);
            c += __shfl_down_sync(0xFFFFFFFFu, c, off);
        }
        if (lane == 0) { s_loss[warp] = l; s_cnt[warp] = c; }
        __syncthreads();
        if (tid == 0) {
            double L = 0.0; unsigned int C = 0u;
            #pragma unroll
            for (int w = 0; w < 4; w++) { L += s_loss[w]; C += s_cnt[w]; }
            double Cd = (double)C;
            if (Cd < 1.0) Cd = 1.0;
            out[0] = (float)(LOSS_W * L / Cd);
            g_done = 0;
        }
    }
}

// ---------------------------------------------------------------------------
extern "C" void kernel_launch(void* const* d_in, const int* in_sizes, int n_in,
                              void* d_out, int out_size)
{
    const float* emb    = (const float*)d_in[0];
    const int*   frames = (const int*)d_in[1];
    const int*   vids   = (const int*)d_in[2];
    float*       out    = (float*)d_out;

    static bool attr_set = false;
    if (!attr_set) {
        cudaFuncSetAttribute(main_kernel,
                             cudaFuncAttributeMaxDynamicSharedMemorySize,
                             SMEM_BYTES);
        attr_set = true;
    }

    main_kernel<<<NBLK, NTHR, SMEM_BYTES>>>(emb, frames, vids, out);
}

// round 16
// speedup vs baseline: 1.9518x; 1.1168x over previous
#include <cuda_runtime.h>
#include <cuda_bf16.h>

#define B_FIXED  4096
#define D_FIXED  256
#define MAX_GAP  5
#define LOSS_W   0.1
#define NBLK     128
#define NTHR     1024
#define NWARP    (NTHR / 32)            // 32
#define NCBIN    2048                   // coarse bin = key>>3 (8 frames/bin)
#define NCW      (NCBIN / 2)            // u16-packed: 1024 words
#define PAIR_CAP 1024
#define POS_PER_BLK (B_FIXED / NBLK)    // 32

__device__ double       g_ploss[NBLK];
__device__ unsigned int g_pcnt[NBLK];
__device__ unsigned int g_done;

__device__ __forceinline__ float pair_dist2(const float* __restrict__ emb,
                                            unsigned int pk, int lane)
{
    const int i = (pk >> 12) & 0xFFF;
    const int j = pk & 0xFFF;
    const float4* ri = (const float4*)(emb + (size_t)i * D_FIXED);
    const float4* rj = (const float4*)(emb + (size_t)j * D_FIXED);
    float4 a0 = __ldg(&ri[lane]);        float4 b0 = __ldg(&rj[lane]);
    float4 a1 = __ldg(&ri[lane + 32]);   float4 b1 = __ldg(&rj[lane + 32]);
    float d0 = a0.x - b0.x, d1 = a0.y - b0.y;
    float d2 = a0.z - b0.z, d3 = a0.w - b0.w;
    float acc = d0 * d0;
    acc = fmaf(d1, d1, acc); acc = fmaf(d2, d2, acc); acc = fmaf(d3, d3, acc);
    d0 = a1.x - b1.x; d1 = a1.y - b1.y; d2 = a1.z - b1.z; d3 = a1.w - b1.w;
    acc = fmaf(d0, d0, acc); acc = fmaf(d1, d1, acc);
    acc = fmaf(d2, d2, acc); acc = fmaf(d3, d3, acc);
    #pragma unroll
    for (int off = 16; off > 0; off >>= 1)
        acc += __shfl_down_sync(0xFFFFFFFFu, acc, off);
    return acc;
}

__global__ void __launch_bounds__(NTHR)
main_kernel(const float* __restrict__ emb,
            const int*   __restrict__ frames,
            const int*   __restrict__ vids,
            float*       __restrict__ out)
{
    // Static smem (~25 KB)
    __shared__ unsigned int bins[NCW];        //  4 KB packed u16 counters/offsets
    __shared__ unsigned int sdata[B_FIXED];   // 16 KB sorted (key<<16 | id)
    __shared__ unsigned int pairs[PAIR_CAP];  //  4 KB
    __shared__ int          s_np;
    __shared__ int          s_scan[NWARP];
    __shared__ double       s_loss[NWARP];
    __shared__ unsigned int s_cnt[NWARP];
    __shared__ bool         s_last;

    const int tid  = threadIdx.x;
    const int warp = tid >> 5;
    const int lane = tid & 31;

    // ---- 1. zero counters (1024 words) ----
    if (tid < NCW / 4)
        ((uint4*)bins)[tid] = make_uint4(0, 0, 0, 0);
    if (tid == 0) s_np = 0;
    __syncthreads();

    // ---- 2. histogram into coarse bins: 1 int4 group (4 elems) per thread ----
    int k0, k1, k2, k3;
    {
        const int4* f4 = (const int4*)frames;
        const int4* v4 = (const int4*)vids;
        int4 f = __ldg(&f4[tid]);
        int4 v = __ldg(&v4[tid]);
        k0 = (v.x << 10) | f.x;
        k1 = (v.y << 10) | f.y;
        k2 = (v.z << 10) | f.z;
        k3 = (v.w << 10) | f.w;
        const int c0 = k0 >> 3, c1 = k1 >> 3, c2 = k2 >> 3, c3 = k3 >> 3;
        atomicAdd(&bins[c0 >> 1], 1u << ((c0 & 1) * 16));
        atomicAdd(&bins[c1 >> 1], 1u << ((c1 & 1) * 16));
        atomicAdd(&bins[c2 >> 1], 1u << ((c2 & 1) * 16));
        atomicAdd(&bins[c3 >> 1], 1u << ((c3 & 1) * 16));
    }
    __syncthreads();

    // ---- 3. exclusive prefix sum: single pass (1 word per thread) ----
    {
        unsigned int word = bins[tid];       // NCW == NTHR
        unsigned int lo = word & 0xFFFFu, hi = word >> 16;
        unsigned int s  = lo + hi;
        unsigned int v  = s;
        #pragma unroll
        for (int off = 1; off < 32; off <<= 1) {
            unsigned int n = __shfl_up_sync(0xFFFFFFFFu, v, off);
            if (lane >= off) v += n;
        }
        if (lane == 31) s_scan[warp] = (int)v;
        __syncthreads();
        if (warp == 0) {                    // NWARP==32: full-warp scan
            unsigned int wv = (unsigned int)s_scan[lane];
            unsigned int orig = wv;
            #pragma unroll
            for (int off = 1; off < 32; off <<= 1) {
                unsigned int n = __shfl_up_sync(0xFFFFFFFFu, wv, off);
                if (lane >= off) wv += n;
            }
            s_scan[lane] = (int)(wv - orig);
        }
        __syncthreads();
        unsigned int run = (unsigned int)s_scan[warp];
        unsigned int plo = run + (v - s);
        unsigned int phi = plo + lo;
        bins[tid] = plo | (phi << 16);      // exclusive start offsets
    }
    __syncthreads();

    // ---- 4. scatter: fetch-inc on packed offsets; store key<<16|id ----
    {
        const int ks[4] = { k0, k1, k2, k3 };
        #pragma unroll
        for (int u = 0; u < 4; u++) {
            const int k  = ks[u];
            const int c  = k >> 3;
            const int sh = (c & 1) * 16;
            unsigned int prev = atomicAdd(&bins[c >> 1], 1u << sh);
            int pos = (int)((prev >> sh) & 0xFFFFu);
            sdata[pos] = ((unsigned int)k << 16) | (unsigned int)(tid * 4 + u);
        }
    }
    __syncthreads();                         // bins now hold END offsets

    // ---- 5. enumerate: 32 owned elements; scan range [start(c), end(c+1)) ----
    if (tid < POS_PER_BLK) {
        const int e = blockIdx.x * POS_PER_BLK + tid;
        const int k = (__ldg(&vids[e]) << 10) | __ldg(&frames[e]);
        const int c = k >> 3;                // <= 2044 (frame <= 999)
        auto endof = [&](int x) -> int {
            unsigned int w = bins[x >> 1];
            return (int)((w >> ((x & 1) * 16)) & 0xFFFFu);
        };
        const int start = (c == 0) ? 0 : endof(c - 1);
        const int stop  = endof(c + 1);      // covers bins c and c+1
        for (int pos = start; pos < stop; pos++) {
            const unsigned int w = sdata[pos];
            const int kx = (int)(w >> 16);
            const int ix = (int)(w & 0xFFFFu);
            const int dk = kx - k;
            // each unordered pair emitted once: smaller key emits forward;
            // equal keys emit toward smaller index
            if ((dk > 0 && dk <= MAX_GAP) || (dk == 0 && ix < e)) {
                int idx = atomicAdd(&s_np, 1);
                if (idx < PAIR_CAP)
                    pairs[idx] = ((unsigned int)dk << 24)
                               | ((unsigned int)e << 12) | (unsigned int)ix;
            }
        }
    }
    __syncthreads();

    // ---- 6. drain: each warp processes TWO pairs concurrently ----
    double       loss = 0.0;
    unsigned int cnt_acc = 0;
    {
        const int np = min(s_np, PAIR_CAP);
        for (int p = warp; p < np; p += 2 * NWARP) {
            const int p2 = p + NWARP;
            const unsigned int pk0 = pairs[p];
            const unsigned int pk1 = (p2 < np) ? pairs[p2] : pk0;

            float acc0 = pair_dist2(emb, pk0, lane);
            float acc1 = pair_dist2(emb, pk1, lane);

            if (lane == 0) {
                float w0 = 1.0f / (1.0f + (float)(pk0 >> 24));
                loss += (double)(acc0 * w0 * (1.0f / (float)D_FIXED));
                cnt_acc += 1u;
                if (p2 < np) {
                    float w1 = 1.0f / (1.0f + (float)(pk1 >> 24));
                    loss += (double)(acc1 * w1 * (1.0f / (float)D_FIXED));
                    cnt_acc += 1u;
                }
            }
        }
    }

    // ---- 7. block reduction ----
    #pragma unroll
    for (int off = 16; off > 0; off >>= 1) {
        loss    += __shfl_down_sync(0xFFFFFFFFu, loss, off);
        cnt_acc += __shfl_down_sync(0xFFFFFFFFu, cnt_acc, off);
    }
    if (lane == 0) { s_loss[warp] = loss; s_cnt[warp] = cnt_acc; }
    __syncthreads();

    if (warp == 0) {                          // NWARP==32: full-warp reduce
        double       l = s_loss[lane];
        unsigned int c = s_cnt[lane];
        #pragma unroll
        for (int off = 16; off > 0; off >>= 1) {
            l += __shfl_down_sync(0xFFFFFFFFu, l, off);
            c += __shfl_down_sync(0xFFFFFFFFu, c, off);
        }
        if (lane == 0) { g_ploss[blockIdx.x] = l; g_pcnt[blockIdx.x] = c; }
    }

    // ---- 8. last-block-done grid reduction ----
    __threadfence();
    if (tid == 0) {
        unsigned int prev = atomicAdd(&g_done, 1u);
        s_last = (prev == NBLK - 1);
    }
    __syncthreads();

    if (s_last) {
        __threadfence();
        double       l = (tid < NBLK) ? g_ploss[tid] : 0.0;
        unsigned int c = (tid < NBLK) ? g_pcnt[tid]  : 0u;
        #pragma unroll
        for (int off = 16; off > 0; off >>= 1) {
            l += __shfl_down_sync(0xFFFFFFFFu, l, off);
            c += __shfl_down_sync(0xFFFFFFFFu, c, off);
        }
        if (lane == 0) { s_loss[warp] = l; s_cnt[warp] = c; }
        __syncthreads();
        if (tid == 0) {
            double L = 0.0; unsigned int C = 0u;
            #pragma unroll
            for (int w = 0; w < 4; w++) { L += s_loss[w]; C += s_cnt[w]; }
            double Cd = (double)C;
            if (Cd < 1.0) Cd = 1.0;
            out[0] = (float)(LOSS_W * L / Cd);
            g_done = 0;
        }
    }
}

// ---------------------------------------------------------------------------
extern "C" void kernel_launch(void* const* d_in, const int* in_sizes, int n_in,
                              void* d_out, int out_size)
{
    const float* emb    = (const float*)d_in[0];
    const int*   frames = (const int*)d_in[1];
    const int*   vids   = (const int*)d_in[2];
    float*       out    = (float*)d_out;

    main_kernel<<<NBLK, NTHR>>>(emb, frames, vids, out);
}

// round 17
// speedup vs baseline: 1.9820x; 1.0155x over previous
#include <cuda_runtime.h>
#include <cuda_bf16.h>

#define B_FIXED  4096
#define D_FIXED  256
#define MAX_GAP  5
#define LOSS_W   0.1
#define NBLK     128
#define NTHR     1024
#define NWARP    (NTHR / 32)            // 32
#define NCBIN    2048                   // coarse bin = key>>3 (8 frames/bin)
#define NCW      (NCBIN / 2)            // u16-packed: 1024 words == NTHR
#define PAIR_CAP 1024
#define POS_PER_BLK (B_FIXED / NBLK)    // 32

__device__ double       g_ploss[NBLK];
__device__ unsigned int g_pcnt[NBLK];
__device__ unsigned int g_done;

__device__ __forceinline__ float pair_dist2(const float* __restrict__ emb,
                                            unsigned int pk, int lane)
{
    const int i = (pk >> 12) & 0xFFF;
    const int j = pk & 0xFFF;
    const float4* ri = (const float4*)(emb + (size_t)i * D_FIXED);
    const float4* rj = (const float4*)(emb + (size_t)j * D_FIXED);
    float4 a0 = __ldg(&ri[lane]);        float4 b0 = __ldg(&rj[lane]);
    float4 a1 = __ldg(&ri[lane + 32]);   float4 b1 = __ldg(&rj[lane + 32]);
    float d0 = a0.x - b0.x, d1 = a0.y - b0.y;
    float d2 = a0.z - b0.z, d3 = a0.w - b0.w;
    float acc = d0 * d0;
    acc = fmaf(d1, d1, acc); acc = fmaf(d2, d2, acc); acc = fmaf(d3, d3, acc);
    d0 = a1.x - b1.x; d1 = a1.y - b1.y; d2 = a1.z - b1.z; d3 = a1.w - b1.w;
    acc = fmaf(d0, d0, acc); acc = fmaf(d1, d1, acc);
    acc = fmaf(d2, d2, acc); acc = fmaf(d3, d3, acc);
    #pragma unroll
    for (int off = 16; off > 0; off >>= 1)
        acc += __shfl_down_sync(0xFFFFFFFFu, acc, off);
    return acc;
}

__global__ void __launch_bounds__(NTHR)
main_kernel(const float* __restrict__ emb,
            const int*   __restrict__ frames,
            const int*   __restrict__ vids,
            float*       __restrict__ out)
{
    __shared__ unsigned int bins[NCW];        //  4 KB packed u16 offsets
    __shared__ unsigned int sdata[B_FIXED];   // 16 KB sorted (key<<16 | id)
    __shared__ unsigned int pairs[PAIR_CAP];  //  4 KB
    __shared__ int          s_mykeys[POS_PER_BLK];
    __shared__ int          s_np;
    __shared__ int          s_scan[NWARP];
    __shared__ double       s_loss[NWARP];
    __shared__ unsigned int s_cnt[NWARP];
    __shared__ bool         s_last;

    const int tid  = threadIdx.x;
    const int warp = tid >> 5;
    const int lane = tid & 31;

    // ---- 1. issue global loads FIRST (latency hidden behind zeroing) ----
    const int4 f = __ldg(&((const int4*)frames)[tid]);
    const int4 v = __ldg(&((const int4*)vids)[tid]);

    // zero counters while loads are in flight
    if (tid < NCW / 4)
        ((uint4*)bins)[tid] = make_uint4(0, 0, 0, 0);
    if (tid == 0) s_np = 0;

    const int k0 = (v.x << 10) | f.x;
    const int k1 = (v.y << 10) | f.y;
    const int k2 = (v.z << 10) | f.z;
    const int k3 = (v.w << 10) | f.w;

    // stash this block's OWN 32 element keys (threads 8b..8b+7 hold them)
    if ((tid >> 3) == blockIdx.x) {
        const int q = (tid & 7) * 4;
        s_mykeys[q]     = k0;
        s_mykeys[q + 1] = k1;
        s_mykeys[q + 2] = k2;
        s_mykeys[q + 3] = k3;
    }
    __syncthreads();                                      // (1)

    // ---- 2. histogram into coarse bins ----
    {
        const int c0 = k0 >> 3, c1 = k1 >> 3, c2 = k2 >> 3, c3 = k3 >> 3;
        atomicAdd(&bins[c0 >> 1], 1u << ((c0 & 1) * 16));
        atomicAdd(&bins[c1 >> 1], 1u << ((c1 & 1) * 16));
        atomicAdd(&bins[c2 >> 1], 1u << ((c2 & 1) * 16));
        atomicAdd(&bins[c3 >> 1], 1u << ((c3 & 1) * 16));
    }
    __syncthreads();                                      // (2)

    // ---- 3. exclusive prefix sum (redundant inter-warp scan: 1 less sync) ----
    {
        unsigned int word = bins[tid];                    // NCW == NTHR
        unsigned int lo = word & 0xFFFFu, hi = word >> 16;
        unsigned int s  = lo + hi;
        unsigned int vv = s;
        #pragma unroll
        for (int off = 1; off < 32; off <<= 1) {
            unsigned int n = __shfl_up_sync(0xFFFFFFFFu, vv, off);
            if (lane >= off) vv += n;
        }
        if (lane == 31) s_scan[warp] = (int)vv;
        __syncthreads();                                  // (3)

        // every warp redundantly scans s_scan; takes prefix at (warp-1)
        unsigned int wv = (unsigned int)s_scan[lane];
        #pragma unroll
        for (int off = 1; off < 32; off <<= 1) {
            unsigned int n = __shfl_up_sync(0xFFFFFFFFu, wv, off);
            if (lane >= off) wv += n;
        }
        unsigned int run = (warp == 0) ? 0u
                         : __shfl_sync(0xFFFFFFFFu, wv, warp - 1);

        unsigned int plo = run + (vv - s);
        unsigned int phi = plo + lo;
        bins[tid] = plo | (phi << 16);                    // exclusive starts
    }
    __syncthreads();                                      // (4)

    // ---- 4. scatter: fetch-inc; store key<<16 | id ----
    {
        const int ks[4] = { k0, k1, k2, k3 };
        #pragma unroll
        for (int u = 0; u < 4; u++) {
            const int k  = ks[u];
            const int c  = k >> 3;
            const int sh = (c & 1) * 16;
            unsigned int prev = atomicAdd(&bins[c >> 1], 1u << sh);
            int pos = (int)((prev >> sh) & 0xFFFFu);
            sdata[pos] = ((unsigned int)k << 16) | (unsigned int)(tid * 4 + u);
        }
    }
    __syncthreads();                                      // (5) bins = END offsets

    // ---- 5. enumerate: 32 owned elements; scan [start(c), end(c+1)) ----
    if (tid < POS_PER_BLK) {
        const int e = blockIdx.x * POS_PER_BLK + tid;
        const int k = s_mykeys[tid];
        const int c = k >> 3;                             // <= 2044
        auto endof = [&](int x) -> int {
            unsigned int w = bins[x >> 1];
            return (int)((w >> ((x & 1) * 16)) & 0xFFFFu);
        };
        const int start = (c == 0) ? 0 : endof(c - 1);
        const int stop  = endof(c + 1);
        for (int pos = start; pos < stop; pos++) {
            const unsigned int w = sdata[pos];
            const int kx = (int)(w >> 16);
            const int ix = (int)(w & 0xFFFFu);
            const int dk = kx - k;
            if ((dk > 0 && dk <= MAX_GAP) || (dk == 0 && ix < e)) {
                int idx = atomicAdd(&s_np, 1);
                if (idx < PAIR_CAP)
                    pairs[idx] = ((unsigned int)dk << 24)
                               | ((unsigned int)e << 12) | (unsigned int)ix;
            }
        }
    }
    __syncthreads();                                      // (6)

    // ---- 6. drain: dual-pair per warp ----
    double       loss = 0.0;
    unsigned int cnt_acc = 0;
    {
        const int np = min(s_np, PAIR_CAP);
        for (int p = warp; p < np; p += 2 * NWARP) {
            const int p2 = p + NWARP;
            const unsigned int pk0 = pairs[p];
            const unsigned int pk1 = (p2 < np) ? pairs[p2] : pk0;

            float acc0 = pair_dist2(emb, pk0, lane);
            float acc1 = pair_dist2(emb, pk1, lane);

            if (lane == 0) {
                float w0 = 1.0f / (1.0f + (float)(pk0 >> 24));
                loss += (double)(acc0 * w0 * (1.0f / (float)D_FIXED));
                cnt_acc += 1u;
                if (p2 < np) {
                    float w1 = 1.0f / (1.0f + (float)(pk1 >> 24));
                    loss += (double)(acc1 * w1 * (1.0f / (float)D_FIXED));
                    cnt_acc += 1u;
                }
            }
        }
    }

    // ---- 7. block reduction: values live ONLY on lane 0 -> direct write ----
    if (lane == 0) { s_loss[warp] = loss; s_cnt[warp] = cnt_acc; }
    __syncthreads();                                      // (7)

    if (warp == 0) {                                      // full-warp reduce
        double       l = s_loss[lane];
        unsigned int c = s_cnt[lane];
        #pragma unroll
        for (int off = 16; off > 0; off >>= 1) {
            l += __shfl_down_sync(0xFFFFFFFFu, l, off);
            c += __shfl_down_sync(0xFFFFFFFFu, c, off);
        }
        if (lane == 0) { g_ploss[blockIdx.x] = l; g_pcnt[blockIdx.x] = c; }
    }

    // ---- 8. last-block-done grid reduction ----
    __threadfence();
    if (tid == 0) {
        unsigned int prev = atomicAdd(&g_done, 1u);
        s_last = (prev == NBLK - 1);
    }
    __syncthreads();                                      // (8)

    if (s_last) {
        __threadfence();
        double       l = (tid < NBLK) ? g_ploss[tid] : 0.0;
        unsigned int c = (tid < NBLK) ? g_pcnt[tid]  : 0u;
        #pragma unroll
        for (int off = 16; off > 0; off >>= 1) {
            l += __shfl_down_sync(0xFFFFFFFFu, l, off);
            c += __shfl_down_sync(0xFFFFFFFFu, c, off);
        }
        if (lane == 0) { s_loss[warp] = l; s_cnt[warp] = c; }
        __syncthreads();
        if (tid == 0) {
            double L = 0.0; unsigned int C = 0u;
            #pragma unroll
            for (int w = 0; w < 4; w++) { L += s_loss[w]; C += s_cnt[w]; }
            double Cd = (double)C;
            if (Cd < 1.0) Cd = 1.0;
            out[0] = (float)(LOSS_W * L / Cd);
            g_done = 0;
        }
    }
}

// ---------------------------------------------------------------------------
extern "C" void kernel_launch(void* const* d_in, const int* in_sizes, int n_in,
                              void* d_out, int out_size)
{
    const float* emb    = (const float*)d_in[0];
    const int*   frames = (const int*)d_in[1];
    const int*   vids   = (const int*)d_in[2];
    float*       out    = (float*)d_out;

    main_kernel<<<NBLK, NTHR>>>(emb, frames, vids, out);
}